// round 2
// baseline (speedup 1.0000x reference)
#include <cuda_runtime.h>
#include <cuda_bf16.h>

// ---------------------------------------------------------------------------
// HeteroRGCN layer:
//   h_item = mean over clicks edges     of (feat_user @ W_clicks.T   + b_clicks)[src]
//   h_user = mean over clicked_by edges of (feat_item @ W_clicked_by.T + b_clicked_by)[src]
// Output layout: [h_user (N_USER x 64), h_item (N_ITEM x 64)] float32.
// ---------------------------------------------------------------------------

#define MAXN 100000

// Scratch (device globals: no allocation allowed in kernel_launch)
__device__ float g_Wh_user[MAXN * 64];   // Linear(feat_user)  for clicks relation
__device__ float g_Wh_item[MAXN * 64];   // Linear(feat_item)  for clicked_by relation
__device__ float g_deg_user[MAXN];
__device__ float g_deg_item[MAXN];

// ---------------------------------------------------------------------------
// Zero out d_out and degree arrays (d_out is poisoned 0xAA before timing).
// ---------------------------------------------------------------------------
__global__ void zero_kernel(float* __restrict__ out, int out_n, int n_user, int n_item) {
    int total = out_n + n_user + n_item;
    for (int i = blockIdx.x * blockDim.x + threadIdx.x; i < total;
         i += gridDim.x * blockDim.x) {
        if (i < out_n) {
            out[i] = 0.0f;
        } else if (i < out_n + n_user) {
            g_deg_user[i - out_n] = 0.0f;
        } else {
            g_deg_item[i - out_n - n_user] = 0.0f;
        }
    }
}

// ---------------------------------------------------------------------------
// Wh = X @ W^T + b   (X: [N,64], W: [64,64] row-major, b: [64])
// Block: 256 threads handles 16 rows x 64 cols. W cached in smem (padded to
// kill bank conflicts), X tile in smem (broadcast reads within warp).
// sel: 0 -> g_Wh_user, 1 -> g_Wh_item
// ---------------------------------------------------------------------------
__global__ void linear_kernel(const float4* __restrict__ X,
                              const float4* __restrict__ W,
                              const float*  __restrict__ b,
                              int N, int sel) {
    __shared__ float4 Ws[64][17];   // W[c][k4], padded stride -> conflict-free
    __shared__ float4 Xs[16][17];
    __shared__ float  bs[64];

    float* out = sel ? g_Wh_item : g_Wh_user;

    int tid = threadIdx.x;

    // Load W (64 rows x 16 float4)
    for (int i = tid; i < 64 * 16; i += 256) {
        Ws[i >> 4][i & 15] = W[i];
    }
    if (tid < 64) bs[tid] = b[tid];

    int row0 = blockIdx.x * 16;
    {
        int r  = tid >> 4;      // 0..15
        int kk = tid & 15;      // 0..15
        int grow = row0 + r;
        Xs[r][kk] = (grow < N) ? X[(long long)grow * 16 + kk]
                               : make_float4(0.f, 0.f, 0.f, 0.f);
    }
    __syncthreads();

    int c    = tid & 63;        // output column
    int rsub = tid >> 6;        // 0..3 -> rows 4*rsub .. 4*rsub+3

    float acc0 = bs[c], acc1 = bs[c], acc2 = bs[c], acc3 = bs[c];

#pragma unroll
    for (int k = 0; k < 16; k++) {
        float4 w  = Ws[c][k];
        float4 x0 = Xs[4 * rsub + 0][k];
        float4 x1 = Xs[4 * rsub + 1][k];
        float4 x2 = Xs[4 * rsub + 2][k];
        float4 x3 = Xs[4 * rsub + 3][k];
        acc0 += x0.x * w.x + x0.y * w.y + x0.z * w.z + x0.w * w.w;
        acc1 += x1.x * w.x + x1.y * w.y + x1.z * w.z + x1.w * w.w;
        acc2 += x2.x * w.x + x2.y * w.y + x2.z * w.z + x2.w * w.w;
        acc3 += x3.x * w.x + x3.y * w.y + x3.z * w.z + x3.w * w.w;
    }

    int rr = row0 + 4 * rsub;
    if (rr + 0 < N) out[(long long)(rr + 0) * 64 + c] = acc0;
    if (rr + 1 < N) out[(long long)(rr + 1) * 64 + c] = acc1;
    if (rr + 2 < N) out[(long long)(rr + 2) * 64 + c] = acc2;
    if (rr + 3 < N) out[(long long)(rr + 3) * 64 + c] = acc3;
}

// ---------------------------------------------------------------------------
// Edge scatter: for each edge e, out[dst[e]] += Wh[src[e]], deg[dst[e]] += 1.
// 16 threads per edge, one float4 each, vector red.global.add.v4.f32.
// whsel: 0 -> gather g_Wh_user, 1 -> g_Wh_item
// degsel: 0 -> g_deg_user, 1 -> g_deg_item
// ---------------------------------------------------------------------------
__global__ void scatter_kernel(const int* __restrict__ src,
                               const int* __restrict__ dst,
                               float4* __restrict__ out,
                               int E, int whsel, int degsel) {
    const float4* Wh = whsel ? (const float4*)g_Wh_item : (const float4*)g_Wh_user;
    float* deg = degsel ? g_deg_item : g_deg_user;

    int idx = blockIdx.x * blockDim.x + threadIdx.x;
    int e = idx >> 4;
    int q = idx & 15;
    if (e >= E) return;

    int s = __ldg(src + e);
    int d = __ldg(dst + e);

    float4 v = __ldg(Wh + (long long)s * 16 + q);
    float4* p = out + (long long)d * 16 + q;
    asm volatile("red.global.add.v4.f32 [%0], {%1, %2, %3, %4};"
                 :: "l"(p), "f"(v.x), "f"(v.y), "f"(v.z), "f"(v.w)
                 : "memory");

    if (q == 0) atomicAdd(deg + d, 1.0f);   // compiles to RED (no return use)
}

// ---------------------------------------------------------------------------
// Divide accumulated sums by max(deg, 1) in place. One thread per float4.
// ---------------------------------------------------------------------------
__global__ void finalize_kernel(float4* __restrict__ out, int N, int degsel) {
    const float* deg = degsel ? g_deg_item : g_deg_user;
    int idx = blockIdx.x * blockDim.x + threadIdx.x;
    if (idx >= N * 16) return;
    int n = idx >> 4;
    float inv = 1.0f / fmaxf(deg[n], 1.0f);
    float4 v = out[idx];
    v.x *= inv; v.y *= inv; v.z *= inv; v.w *= inv;
    out[idx] = v;
}

// ---------------------------------------------------------------------------
extern "C" void kernel_launch(void* const* d_in, const int* in_sizes, int n_in,
                              void* d_out, int out_size) {
    const float* feat_user   = (const float*)d_in[0];
    const float* feat_item   = (const float*)d_in[1];
    const int*   src_clicks  = (const int*)d_in[2];
    const int*   dst_clicks  = (const int*)d_in[3];
    const int*   src_cb      = (const int*)d_in[4];
    const int*   dst_cb      = (const int*)d_in[5];
    const float* W_clicks    = (const float*)d_in[6];
    const float* b_clicks    = (const float*)d_in[7];
    const float* W_cb        = (const float*)d_in[8];
    const float* b_cb        = (const float*)d_in[9];

    int n_user = in_sizes[0] / 64;
    int n_item = in_sizes[1] / 64;
    int E1 = in_sizes[2];   // clicks edges
    int E2 = in_sizes[4];   // clicked_by edges

    float* out = (float*)d_out;
    float* out_user = out;                              // [n_user, 64]
    float* out_item = out + (long long)n_user * 64;     // [n_item, 64]

    // 1. Zero output + degree arrays
    zero_kernel<<<2048, 256>>>(out, out_size, n_user, n_item);

    // 2. Per-relation linear transforms
    linear_kernel<<<(n_user + 15) / 16, 256>>>(
        (const float4*)feat_user, (const float4*)W_clicks, b_clicks, n_user, /*sel=*/0);
    linear_kernel<<<(n_item + 15) / 16, 256>>>(
        (const float4*)feat_item, (const float4*)W_cb, b_cb, n_item, /*sel=*/1);

    // 3. Edge scatter-add (vector reductions)
    // clicks: user -> item  (gather Wh_user, accumulate into out_item / deg_item)
    {
        int threads = 256;
        long long total = (long long)E1 * 16;
        int blocks = (int)((total + threads - 1) / threads);
        scatter_kernel<<<blocks, threads>>>(src_clicks, dst_clicks,
                                            (float4*)out_item, E1,
                                            /*whsel=*/0, /*degsel=*/1);
    }
    // clicked_by: item -> user (gather Wh_item, accumulate into out_user / deg_user)
    {
        int threads = 256;
        long long total = (long long)E2 * 16;
        int blocks = (int)((total + threads - 1) / threads);
        scatter_kernel<<<blocks, threads>>>(src_cb, dst_cb,
                                            (float4*)out_user, E2,
                                            /*whsel=*/1, /*degsel=*/0);
    }

    // 4. Mean
    finalize_kernel<<<(n_user * 16 + 255) / 256, 256>>>((float4*)out_user, n_user, /*degsel=*/0);
    finalize_kernel<<<(n_item * 16 + 255) / 256, 256>>>((float4*)out_item, n_item, /*degsel=*/1);
}